// round 17
// baseline (speedup 1.0000x reference)
#include <cuda_runtime.h>
#include <cstdint>
#include <cstddef>

// Problem constants
#define NUM_LUT 3
#define GDIM    1024      // G = IN_F / VEC
#define OUTF    4096
#define SLUT    16
#define VEC     4
#define NGRP    32        // NG = IN_F / GROUP (GROUP = 32 g's)

// Tiling: block = 8 warps; each warp owns 8 consecutive o's.
// Block processes TWO 8-g tiles back-to-back (warp-local flush between them,
// no block barrier anywhere), amortizing setup and halving tile-boundary
// demand gaps. Both tiles lie in the same 32-g quant group.
#define NTHREADS 256
#define O_PER_WARP 8
#define OTILE (8 * O_PER_WARP)   // 64 o per block
#define GTILE_J 8                // g's per inner tile
#define TILES   2                // g-tiles per block

// Staging tile: [64 o][stride 36 words]; row holds 8 j * 4 part = 32 floats
// + 4 pad. Stride 36 => STS bank = (o_sub*4 + part) mod 32, distinct for all
// 32 lanes (conflict-free). Reused across the 2 tiles (warp-local hazards
// only; ordered by __syncwarp + program order).
#define SROW 36

// Per-LUT argmax over 16 gate values spread across a quad (4 floats/lane):
//  1) local max via 2-level fmaxf tree; local index via ordered equality
//     chain resolved IN PARALLEL with the shfl chain (first match = first
//     occurrence, exact).
//  2) quad max by VALUE only: 2x shfl.bfly + fmaxf (bit-exact, NaN-free data)
//  3) ballot (full-warp uniform mask); lowest set lane in my quad's nibble =
//     exact first-occurrence winner
//  4) one shfl.idx fetches the winner's local index
// Bit-exact vs jnp.argmax first-index tie semantics.
#define DO_LUT(v, L, g, accv)                                                 \
    {                                                                         \
        const float m = fmaxf(fmaxf((v).x, (v).y), fmaxf((v).z, (v).w));      \
        float q = fmaxf(m, __shfl_xor_sync(0xffffffffu, m, 1));               \
        q = fmaxf(q, __shfl_xor_sync(0xffffffffu, q, 2));                     \
        const int mi = ((v).x == m) ? 0 : ((v).y == m) ? 1                    \
                     : ((v).z == m) ? 2 : 3;                                  \
        const unsigned bal = __ballot_sync(0xffffffffu, m == q);              \
        const unsigned nib = (bal >> (lane & 28)) & 0xFu;                     \
        const int wl = (lane & 28) + (__ffs(nib) - 1);                        \
        const int wmi = __shfl_sync(0xffffffffu, mi, wl);                     \
        const int gidx = ((wl & 3) << 2) | wmi;                               \
        (accv) += __ldg(cbk + (((size_t)(L) * GDIM + (g)) * SLUT + gidx) * VEC + part); \
    }

__global__ void __launch_bounds__(NTHREADS, 8)
recon_kernel(const float* __restrict__ gate,
             const float* __restrict__ codebook,
             const float* __restrict__ scales,
             const int*   __restrict__ zeros,
             float*       __restrict__ out)
{
    __shared__ float otile[OTILE * SROW];   // 9216 B, reused across tiles

    const int tid    = threadIdx.x;
    const int wid    = tid >> 5;
    const int lane   = tid & 31;
    const int part   = lane & 3;              // which 16B quarter of the 64B gate row
    const int o_sub  = lane >> 2;             // which of the warp's 8 o's

    const int o0_blk = blockIdx.x * OTILE;
    const int o0     = o0_blk + wid * O_PER_WARP;   // warp's first o
    const int o      = o0 + o_sub;
    const int o_loc  = wid * O_PER_WARP + o_sub;    // 0..63 within block
    const int gb     = blockIdx.y * (GTILE_J * TILES);  // block's first g
    const int ng     = blockIdx.y >> 1;       // quant group (16 g per block, 32 per group)

    const float sc   = scales[o * NGRP + ng];
    const float bias = -((float)zeros[o * NGRP + ng]) * sc;  // out = acc*sc + bias

    const size_t gstep = (size_t)OUTF * SLUT / 4;   // 16384 float4 per g
    const float* cbk = codebook;

    float* myrow = &otile[o_loc * SROW + part];
    const int wrow0 = wid * O_PER_WARP;

    #pragma unroll
    for (int t = 0; t < TILES; ++t) {
        const int g0 = gb + t * GTILE_J;

        // Gate base pointers for this tile (float4 units). For fixed (l,g):
        // warp covers o0..o0+7 -> one contiguous 512B chunk; lane q reads #q.
        const float4* gp0 = reinterpret_cast<const float4*>(gate) +
            (((size_t)0 * GDIM + g0) * OUTF + o0) * (SLUT / 4) + lane;
        const float4* gp1 = reinterpret_cast<const float4*>(gate) +
            (((size_t)1 * GDIM + g0) * OUTF + o0) * (SLUT / 4) + lane;
        const float4* gp2 = reinterpret_cast<const float4*>(gate) +
            (((size_t)2 * GDIM + g0) * OUTF + o0) * (SLUT / 4) + lane;

        #pragma unroll 2
        for (int j = 0; j < GTILE_J; ++j) {
            const int g = g0 + j;

            // Issue all three contiguous 512B streaming loads up front
            const float4 v0 = __ldcs(gp0 + (size_t)j * gstep);
            const float4 v1 = __ldcs(gp1 + (size_t)j * gstep);
            const float4 v2 = __ldcs(gp2 + (size_t)j * gstep);

            float acc = 0.0f;
            DO_LUT(v0, 0, g, acc)
            DO_LUT(v1, 1, g, acc)
            DO_LUT(v2, 2, g, acc)

            // Stage into smem (conflict-free); flushed warp-locally below.
            myrow[j * 4] = fmaf(acc, sc, bias);
        }

        // Warp-local flush: this warp produced rows [wid*8, wid*8+8); only its
        // own lanes read them back -> __syncwarp ordering suffices.
        __syncwarp();
        #pragma unroll
        for (int u = 0; u < 2; ++u) {
            const int idx = lane + u * 32;         // 0..63 within warp tile
            const int ol  = wrow0 + (idx >> 3);    // this warp's o row
            const int jj  = idx & 7;               // 0..7
            // 8-lane group reads one full smem row (8 x 16B = 32 banks,
            // conflict-free) and writes one full, aligned 128B line: no RMW.
            const float4 v = *reinterpret_cast<const float4*>(&otile[ol * SROW + jj * 4]);
            __stcs(reinterpret_cast<float4*>(out) +
                   (size_t)(o0_blk + ol) * (GDIM) + g0 + jj, v);
        }
        // Order flush reads before next tile's staging writes (same warp).
        __syncwarp();
    }
}

extern "C" void kernel_launch(void* const* d_in, const int* in_sizes, int n_in,
                              void* d_out, int out_size) {
    const float* gate     = (const float*)d_in[0];  // [3,1024,4096,16] f32
    const float* codebook = (const float*)d_in[1];  // [3,1024,16,4]   f32
    const float* scales   = (const float*)d_in[2];  // [4096,32]       f32
    const int*   zeros    = (const int*)  d_in[3];  // [4096,32]       i32
    float*       out      = (float*)d_out;          // [4096,4096]     f32

    (void)in_sizes; (void)n_in; (void)out_size;

    dim3 grid(OUTF / OTILE, GDIM / (GTILE_J * TILES));   // (64, 64) = 4096 blocks
    recon_kernel<<<grid, NTHREADS>>>(gate, codebook, scales, zeros, out);
}